// round 14
// baseline (speedup 1.0000x reference)
#include <cuda_runtime.h>
#include <cstdint>

// out[b,h,w,c] = (vector[0,c] >= -5) ? ip1[b,h,w,c] : ip2[b,h,w,c]
// Fixed shape: 16,777,216 f32 = 64 MiB. For N(0,1) vector the mask is all-true
// with probability ~1 -> the op is a pure 64 MiB D2D copy.
//
// R14: copy-engine probe (last untested engine; LDG/256-bit/TMA all converge
// to ~18us on the SM path). Graph = [memcpy node: ip1 -> out] -> [fixup
// kernel]. The fixup reads the 128-float mask, exits immediately when all
// channels are true (~always), otherwise patches the mask-false lanes of out
// from ip2 (deterministic worst case via grid-stride).

static constexpr int N_ELEMS = 32 * 64 * 64 * 128;   // 16,777,216 f32
static constexpr int N4 = N_ELEMS / 4;               // 4,194,304 float4
static constexpr int FIX_THREADS = 256;
static constexpr int FIX_BLOCKS  = 512;

__global__ __launch_bounds__(FIX_THREADS)
void fixup_kernel(const float4* __restrict__ ip2,
                  const float* __restrict__ vec,
                  float4* __restrict__ out)
{
    int tid = threadIdx.x;

    // Hot-path gate: all 256 threads check (tid & 127) covers all channels.
    bool m = vec[tid & 127] >= -5.0f;
    if (__syncthreads_and(m)) return;   // mask all-true: memcpy result stands

    // Cold path (probability ~0): patch channels whose mask is false.
    const float4* v4 = reinterpret_cast<const float4*>(vec);
    int base = blockIdx.x * FIX_THREADS + tid;
    for (int j = base; j < N4; j += FIX_BLOCKS * FIX_THREADS) {
        int g = j & 31;  // float4 channel group
        float4 v = v4[g];
        bool m0 = v.x >= -5.0f;
        bool m1 = v.y >= -5.0f;
        bool m2 = v.z >= -5.0f;
        bool m3 = v.w >= -5.0f;
        if (m0 & m1 & m2 & m3) continue;      // group already correct (ip1)
        float4 b = __ldcg(ip2 + j);
        float4 r = out[j];                    // holds ip1 values from memcpy
        r.x = m0 ? r.x : b.x;
        r.y = m1 ? r.y : b.y;
        r.z = m2 ? r.z : b.z;
        r.w = m3 ? r.w : b.w;
        out[j] = r;
    }
}

extern "C" void kernel_launch(void* const* d_in, const int* in_sizes, int n_in,
                              void* d_out, int out_size)
{
    const float4* ip2 = reinterpret_cast<const float4*>(d_in[1]);
    const float*  vec = reinterpret_cast<const float*>(d_in[2]);  // row 0 used
    float4* out = reinterpret_cast<float4*>(d_out);

    // Unconditional bulk copy ip1 -> out (driver CE / tuned copy path).
    cudaMemcpyAsync(d_out, d_in[0], (size_t)N_ELEMS * sizeof(float),
                    cudaMemcpyDeviceToDevice, 0);

    // Correctness fixup (no-op on the ~always-taken path).
    fixup_kernel<<<FIX_BLOCKS, FIX_THREADS>>>(ip2, vec, out);
}

// round 15
// speedup vs baseline: 1.1969x; 1.1969x over previous
#include <cuda_runtime.h>
#include <cstdint>

// out[b,h,w,c] = (vector[0,c] >= -5) ? ip1[b,h,w,c] : ip2[b,h,w,c]
// Fixed shape: 16,777,216 f32 = 4,194,304 float4 = 2048 blocks x 256 thr x 8.
//
// FINAL (best kernel 17.79/17.95us, reproduced). The mandatory 64 MiB read +
// 64 MiB write mixed HBM stream is the floor: LDG, 256-bit LDG, TMA bulk and
// CE memcpy all converge to the same ~4.5-4.7 TB/s effective equilibrium
// (path-independent), and the full cache-policy matrix is flat. Winning
// structure:
//   - exact tiling, no bounds checks (shape compile-time fixed)
//   - 8 speculative __ldcg loads issued BEFORE the mask resolves (removes the
//     vec-load -> branch -> data-load serial chain; mask ~always selects ip1)
//   - plain .wb stores (best-measured store policy)
//   - thread stride 256 == 0 mod 32 -> fixed float4 channel group per thread

static constexpr int THREADS = 256;
static constexpr int VPT = 8;                       // float4 per thread
static constexpr int N4 = 32 * 64 * 64 * 128 / 4;   // 4,194,304
static constexpr int BLOCKS = N4 / (THREADS * VPT); // 2048, exact

__global__ __launch_bounds__(THREADS)
void random_pick_kernel(const float4* __restrict__ ip1,
                        const float4* __restrict__ ip2,
                        const float* __restrict__ vec,
                        float4* __restrict__ out)
{
    int base = blockIdx.x * (THREADS * VPT) + threadIdx.x;
    int g = base & 31;  // fixed channel group (stride 256 == 0 mod 32)

    // Speculative: issue all 8 data loads immediately; mask load overlaps.
    float4 r[VPT];
    #pragma unroll
    for (int i = 0; i < VPT; i++)
        r[i] = __ldcg(ip1 + base + i * THREADS);

    float4 v = __ldg(reinterpret_cast<const float4*>(vec) + g);
    bool m0 = v.x >= -5.0f;
    bool m1 = v.y >= -5.0f;
    bool m2 = v.z >= -5.0f;
    bool m3 = v.w >= -5.0f;

    if (!(m0 & m1 & m2 & m3)) {
        // Cold path (probability ~0 for N(0,1) vector).
        if (!(m0 | m1 | m2 | m3)) {
            #pragma unroll
            for (int i = 0; i < VPT; i++)
                r[i] = __ldcg(ip2 + base + i * THREADS);
        } else {
            #pragma unroll
            for (int i = 0; i < VPT; i++) {
                float4 b = __ldcg(ip2 + base + i * THREADS);
                r[i].x = m0 ? r[i].x : b.x;
                r[i].y = m1 ? r[i].y : b.y;
                r[i].z = m2 ? r[i].z : b.z;
                r[i].w = m3 ? r[i].w : b.w;
            }
        }
    }

    // Plain .wb stores (best-measured policy).
    #pragma unroll
    for (int i = 0; i < VPT; i++)
        out[base + i * THREADS] = r[i];
}

extern "C" void kernel_launch(void* const* d_in, const int* in_sizes, int n_in,
                              void* d_out, int out_size)
{
    const float4* ip1 = reinterpret_cast<const float4*>(d_in[0]);
    const float4* ip2 = reinterpret_cast<const float4*>(d_in[1]);
    const float*  vec = reinterpret_cast<const float*>(d_in[2]);  // row 0 used
    float4* out = reinterpret_cast<float4*>(d_out);

    random_pick_kernel<<<BLOCKS, THREADS>>>(ip1, ip2, vec, out);
}